// round 15
// baseline (speedup 1.0000x reference)
#include <cuda_runtime.h>
#include <cuda_bf16.h>
#include <cuda_fp16.h>
#include <cstdint>

// Problem constants (fixed by the dataset)
#define N_NODES 100000
#define N_EDGES 1600000
#define N_FEAT  128
#define HIDDEN  64
#define N_OUT   10
#define N_GRAPHS 64

#define SCAN_B 1024
#define N_SCAN_BLOCKS ((N_NODES + SCAN_B - 1) / SCAN_B)   // 98

// ---------------- device scratch (static, no allocation) ----------------
__device__ int    g_deg[N_NODES];
__device__ float  g_dis[N_NODES];
__device__ int    g_rowptr[N_NODES + 1];
__device__ int    g_cursor[N_NODES];
__device__ int    g_scan_tmp[N_NODES];
__device__ int    g_bsum[N_SCAN_BLOCKS];
__device__ __align__(16) int2   g_csr_pack[N_EDGES];
__device__ __align__(16) __half g_tmpAh[(size_t)N_NODES * HIDDEN]; // h@W (fp16)
__device__ __align__(16) __half g_tmpBh[(size_t)N_NODES * HIDDEN]; // agg h (fp16)
__device__ float  g_pool_sums[N_GRAPHS * HIDDEN];
__device__ float  g_pool_cnt[N_GRAPHS];

// ---------------- init / CSR build --------------------------------------
__global__ void init_kernel() {
    int i = blockIdx.x * blockDim.x + threadIdx.x;
    if (i < N_NODES) g_deg[i] = 1;
    if (i < N_GRAPHS * HIDDEN) g_pool_sums[i] = 0.f;
    if (i < N_GRAPHS) g_pool_cnt[i] = 0.f;
}

__global__ void count_kernel(const int* __restrict__ ei) {
    int e = blockIdx.x * blockDim.x + threadIdx.x;
    if (e < N_EDGES) atomicAdd(&g_deg[ei[e + N_EDGES]], 1);
}

__global__ void scan1_kernel() {
    __shared__ int s[SCAN_B];
    int tid = threadIdx.x;
    int i = blockIdx.x * SCAN_B + tid;
    int deg = (i < N_NODES) ? g_deg[i] : 1;
    if (i < N_NODES) g_dis[i] = rsqrtf((float)deg);
    int v = deg - 1;
    s[tid] = v;
    __syncthreads();
    #pragma unroll
    for (int off = 1; off < SCAN_B; off <<= 1) {
        int t = (tid >= off) ? s[tid - off] : 0;
        __syncthreads();
        s[tid] += t;
        __syncthreads();
    }
    if (i < N_NODES) g_scan_tmp[i] = s[tid] - v;
    if (tid == SCAN_B - 1) g_bsum[blockIdx.x] = s[tid];
}

// scan3: warp-parallel block-offset computation (no serial ptr-chase)
__global__ void scan3_kernel() {
    __shared__ int base;
    int tid = threadIdx.x;
    if (tid < 32) {
        int sum = 0;
        for (int b = tid; b < blockIdx.x; b += 32) sum += g_bsum[b];
        #pragma unroll
        for (int o = 16; o > 0; o >>= 1)
            sum += __shfl_down_sync(0xFFFFFFFFu, sum, o);
        if (tid == 0) {
            base = sum;
            if (blockIdx.x == 0) g_rowptr[N_NODES] = N_EDGES;
        }
    }
    __syncthreads();
    int i = blockIdx.x * SCAN_B + tid;
    if (i < N_NODES) {
        int v = g_scan_tmp[i] + base;
        g_rowptr[i] = v;
        g_cursor[i] = v;
    }
}

__global__ void fill_kernel(const int* __restrict__ ei) {
    int e = blockIdx.x * blockDim.x + threadIdx.x;
    if (e < N_EDGES) {
        int r = ei[e];
        int c = ei[e + N_EDGES];
        int pos = atomicAdd(&g_cursor[c], 1);
        float nr = g_dis[r] * g_dis[c];
        g_csr_pack[pos] = make_int2(r, __float_as_int(nr));
    }
}

// ---------------- SGEMM (scalar FFMA, double-buffered A tile) ------------
// C[M,64] = A[M,K] @ W[K,64], fp32 compute, output stored as fp16.
// A = x fp32 (sel==0) or g_tmpBh fp16 (sel==1).
// 128x64 block tile, 256 threads, microtile 8 rows x 4 cols, KC=16 2-stage.
template <int K>
__global__ __launch_bounds__(256, 3)
void gemm_kernel(const float* __restrict__ x, const float* __restrict__ W,
                 int sel, int M) {
    constexpr int KC = 16;
    constexpr int NCH = K / KC;
    constexpr int AST = 132;   // padded word stride per k-row (bank spread)
    __shared__ __align__(16) float Ws[K * 64];
    __shared__ __align__(16) float As[2][KC * AST];

    const __half* __restrict__ Ah16 = g_tmpBh;
    __half* __restrict__ C = g_tmpAh;

    const int tid = threadIdx.x;
    const int tx = tid & 15;    // cols tx*4 .. tx*4+3
    const int ty = tid >> 4;    // rows ty*8 .. ty*8+7
    const int row0 = blockIdx.x * 128;

    for (int i = tid; i < K * 16; i += 256)
        *(float4*)(Ws + i * 4) = *(const float4*)(W + i * 4);

    // prefetch lanes: 512 float4 slots per chunk (128 rows x 4 float4)
    const int lr0 = tid >> 2;            // rows 0..63
    const int lr1 = (tid + 256) >> 2;    // rows 64..127
    const int lq  = tid & 3;             // float4 index along KC

    auto load4 = [&](int row, int kk) -> float4 {
        float4 v = make_float4(0.f, 0.f, 0.f, 0.f);
        int grow = row0 + row;
        if (grow < M) {
            if (sel == 0) {
                v = *(const float4*)(x + (size_t)grow * K + kk);
            } else {
                uint2 pk = *(const uint2*)(Ah16 + (size_t)grow * K + kk);
                __half2 h01 = *(__half2*)&pk.x;
                __half2 h23 = *(__half2*)&pk.y;
                float2 f01 = __half22float2(h01);
                float2 f23 = __half22float2(h23);
                v = make_float4(f01.x, f01.y, f23.x, f23.y);
            }
        }
        return v;
    };

    float4 pre0 = load4(lr0, lq * 4);
    float4 pre1 = load4(lr1, lq * 4);
    {
        float* dst = &As[0][0];
        dst[(lq * 4 + 0) * AST + lr0] = pre0.x;
        dst[(lq * 4 + 1) * AST + lr0] = pre0.y;
        dst[(lq * 4 + 2) * AST + lr0] = pre0.z;
        dst[(lq * 4 + 3) * AST + lr0] = pre0.w;
        dst[(lq * 4 + 0) * AST + lr1] = pre1.x;
        dst[(lq * 4 + 1) * AST + lr1] = pre1.y;
        dst[(lq * 4 + 2) * AST + lr1] = pre1.z;
        dst[(lq * 4 + 3) * AST + lr1] = pre1.w;
    }
    __syncthreads();

    float acc[8][4];
    #pragma unroll
    for (int r = 0; r < 8; r++)
        #pragma unroll
        for (int c = 0; c < 4; c++) acc[r][c] = 0.f;

    #pragma unroll
    for (int c = 0; c < NCH; c++) {
        if (c + 1 < NCH) {
            int kk = (c + 1) * KC + lq * 4;
            pre0 = load4(lr0, kk);
            pre1 = load4(lr1, kk);
        }

        const float* Ab = &As[c & 1][0];
        #pragma unroll
        for (int k = 0; k < KC; k++) {
            const float* ap = Ab + k * AST + ty * 8;
            float4 alo = *(const float4*)(ap);
            float4 ahi = *(const float4*)(ap + 4);
            float4 b   = *(const float4*)(Ws + (size_t)(c * KC + k) * 64 + tx * 4);
            float a[8] = {alo.x, alo.y, alo.z, alo.w, ahi.x, ahi.y, ahi.z, ahi.w};
            #pragma unroll
            for (int r = 0; r < 8; r++) {
                acc[r][0] += a[r] * b.x;
                acc[r][1] += a[r] * b.y;
                acc[r][2] += a[r] * b.z;
                acc[r][3] += a[r] * b.w;
            }
        }

        if (c + 1 < NCH) {
            float* dst = &As[(c + 1) & 1][0];
            dst[(lq * 4 + 0) * AST + lr0] = pre0.x;
            dst[(lq * 4 + 1) * AST + lr0] = pre0.y;
            dst[(lq * 4 + 2) * AST + lr0] = pre0.z;
            dst[(lq * 4 + 3) * AST + lr0] = pre0.w;
            dst[(lq * 4 + 0) * AST + lr1] = pre1.x;
            dst[(lq * 4 + 1) * AST + lr1] = pre1.y;
            dst[(lq * 4 + 2) * AST + lr1] = pre1.z;
            dst[(lq * 4 + 3) * AST + lr1] = pre1.w;
            __syncthreads();
        }
    }

    #pragma unroll
    for (int r = 0; r < 8; r++) {
        int grow = row0 + ty * 8 + r;
        if (grow < M) {
            __half2 h01 = __floats2half2_rn(acc[r][0], acc[r][1]);
            __half2 h23 = __floats2half2_rn(acc[r][2], acc[r][3]);
            uint2 pk;
            pk.x = *(uint32_t*)&h01;
            pk.y = *(uint32_t*)&h23;
            *(uint2*)(C + (size_t)grow * 64 + tx * 4) = pk;
        }
    }
}

// ---------------- aggregation: fp16 gather, fp32 accumulate, fp16 store --
// g_tmpBh[i] = sum_in(tmpAh[src]*norm) + tmpAh[i]/deg + b, optional relu.
// one warp per node; lane owns 2 consecutive features (one half2)
__global__ void aggregate_kernel(const float* __restrict__ bias, int relu) {
    int warp = (blockIdx.x * blockDim.x + threadIdx.x) >> 5;
    if (warp >= N_NODES) return;
    int lane = threadIdx.x & 31;

    const __half* __restrict__ hW = g_tmpAh;
    __half* __restrict__ out = g_tmpBh;

    int start = g_rowptr[warp];
    int end   = g_rowptr[warp + 1];
    float d = g_dis[warp];
    float w = d * d;   // self loop weight = 1/deg

    float2 sf = __half22float2(*(const __half2*)(hW + (size_t)warp * 64 + lane * 2));
    float ax = sf.x * w, ay = sf.y * w;

    for (int k = start; k < end; k++) {
        int2 p = g_csr_pack[k];
        float nr = __int_as_float(p.y);
        float2 vf = __half22float2(*(const __half2*)(hW + (size_t)p.x * 64 + lane * 2));
        ax += vf.x * nr;
        ay += vf.y * nr;
    }

    ax += bias[lane * 2];
    ay += bias[lane * 2 + 1];
    if (relu) { ax = fmaxf(ax, 0.f); ay = fmaxf(ay, 0.f); }
    *(__half2*)(out + (size_t)warp * 64 + lane * 2) = __floats2half2_rn(ax, ay);
}

// ---------------- mean pool over sorted batch (fp16 in, fp32 acc) --------
__global__ void pool_kernel(const int* __restrict__ batch) {
    const __half* __restrict__ h = g_tmpBh;
    int col  = threadIdx.x & 63;
    int slot = threadIdx.x >> 6;
    int n0 = blockIdx.x * 512 + slot * 128;
    if (n0 >= N_NODES) return;
    int n1 = min(n0 + 128, N_NODES);

    float acc = 0.f, cnt = 0.f;
    int cur = batch[n0];
    for (int i = n0; i < n1; i++) {
        int g = batch[i];
        if (g != cur) {
            atomicAdd(&g_pool_sums[cur * 64 + col], acc);
            if (col == 0) atomicAdd(&g_pool_cnt[cur], cnt);
            cur = g; acc = 0.f; cnt = 0.f;
        }
        acc += __half2float(h[(size_t)i * 64 + col]);
        cnt += 1.f;
    }
    atomicAdd(&g_pool_sums[cur * 64 + col], acc);
    if (col == 0) atomicAdd(&g_pool_cnt[cur], cnt);
}

// ---------------- final linear -------------------------------------------
__global__ void final_kernel(const float* __restrict__ Wlin,
                             const float* __restrict__ blin,
                             float* __restrict__ out) {
    int tid = threadIdx.x;
    if (tid >= N_GRAPHS * N_OUT) return;
    int g = tid / N_OUT;
    int o = tid % N_OUT;
    float inv = 1.f / fmaxf(g_pool_cnt[g], 1.f);
    float acc = blin[o];
    #pragma unroll
    for (int c = 0; c < 64; c++)
        acc += g_pool_sums[g * 64 + c] * inv * Wlin[c * N_OUT + o];
    out[g * N_OUT + o] = acc;
}

// ---------------- launch --------------------------------------------------
extern "C" void kernel_launch(void* const* d_in, const int* in_sizes, int n_in,
                              void* d_out, int out_size) {
    const float* x    = (const float*)d_in[0];
    const int*   ei   = (const int*)d_in[1];
    const int*   batch= (const int*)d_in[2];
    const float* W1   = (const float*)d_in[3];
    const float* b1   = (const float*)d_in[4];
    const float* W2   = (const float*)d_in[5];
    const float* b2   = (const float*)d_in[6];
    const float* W3   = (const float*)d_in[7];
    const float* b3   = (const float*)d_in[8];
    const float* Wlin = (const float*)d_in[9];
    const float* blin = (const float*)d_in[10];
    float* out = (float*)d_out;

    const int EBLK = (N_EDGES + 255) / 256;
    const int NBLK = (N_NODES + 255) / 256;
    const int GEMM_BLK = (N_NODES + 127) / 128;
    const int AGG_BLK  = (N_NODES * 32 + 255) / 256;

    // launches 0..2: prep gemm1 doesn't depend on
    init_kernel<<<NBLK, 256>>>();                    // 0
    count_kernel<<<EBLK, 256>>>(ei);                 // 1
    scan1_kernel<<<N_SCAN_BLOCKS, SCAN_B>>>();       // 2

    // launch 3: big GEMM (x @ W1) — ncu capture slot (control)
    gemm_kernel<128><<<GEMM_BLK, 256>>>(x, W1, 0, N_NODES);   // 3

    // finish CSR build
    scan3_kernel<<<N_SCAN_BLOCKS, SCAN_B>>>();       // 4
    fill_kernel<<<EBLK, 256>>>(ei);                  // 5

    // layer 1 aggregation
    aggregate_kernel<<<AGG_BLK, 256>>>(b1, 1);
    // layer 2
    gemm_kernel<64><<<GEMM_BLK, 256>>>(x, W2, 1, N_NODES);
    aggregate_kernel<<<AGG_BLK, 256>>>(b2, 1);
    // layer 3
    gemm_kernel<64><<<GEMM_BLK, 256>>>(x, W3, 1, N_NODES);
    aggregate_kernel<<<AGG_BLK, 256>>>(b3, 0);

    // pool + head
    pool_kernel<<<(N_NODES + 511) / 512, 256>>>(batch);
    final_kernel<<<1, N_GRAPHS * N_OUT>>>(Wlin, blin, out);
}

// round 16
// speedup vs baseline: 1.0166x; 1.0166x over previous
#include <cuda_runtime.h>
#include <cuda_bf16.h>
#include <cuda_fp16.h>
#include <cstdint>

// Problem constants (fixed by the dataset)
#define N_NODES 100000
#define N_EDGES 1600000
#define N_FEAT  128
#define HIDDEN  64
#define N_OUT   10
#define N_GRAPHS 64

#define SCAN_B 1024
#define N_SCAN_BLOCKS ((N_NODES + SCAN_B - 1) / SCAN_B)   // 98

// ---------------- device scratch (static, no allocation) ----------------
__device__ int    g_deg[N_NODES];
__device__ float  g_dis[N_NODES];
__device__ int    g_rowptr[N_NODES + 1];
__device__ int    g_cursor[N_NODES];
__device__ int    g_scan_tmp[N_NODES];
__device__ int    g_bsum[N_SCAN_BLOCKS];
__device__ __align__(16) int2   g_csr_pack[N_EDGES];
__device__ __align__(16) __half g_tmpAh[(size_t)N_NODES * HIDDEN]; // h@W (fp16)
__device__ __align__(16) float  g_tmpB[(size_t)N_NODES * HIDDEN];  // aggregated h
__device__ float  g_pool_sums[N_GRAPHS * HIDDEN];
__device__ float  g_pool_cnt[N_GRAPHS];

// ---------------- init / CSR build --------------------------------------
__global__ void init_kernel() {
    int i = blockIdx.x * blockDim.x + threadIdx.x;
    if (i < N_NODES) g_deg[i] = 1;
    if (i < N_GRAPHS * HIDDEN) g_pool_sums[i] = 0.f;
    if (i < N_GRAPHS) g_pool_cnt[i] = 0.f;
}

__global__ void count_kernel(const int* __restrict__ ei) {
    int e = blockIdx.x * blockDim.x + threadIdx.x;
    if (e < N_EDGES) atomicAdd(&g_deg[ei[e + N_EDGES]], 1);
}

__global__ void scan1_kernel() {
    __shared__ int s[SCAN_B];
    int tid = threadIdx.x;
    int i = blockIdx.x * SCAN_B + tid;
    int deg = (i < N_NODES) ? g_deg[i] : 1;
    if (i < N_NODES) g_dis[i] = rsqrtf((float)deg);
    int v = deg - 1;
    s[tid] = v;
    __syncthreads();
    #pragma unroll
    for (int off = 1; off < SCAN_B; off <<= 1) {
        int t = (tid >= off) ? s[tid - off] : 0;
        __syncthreads();
        s[tid] += t;
        __syncthreads();
    }
    if (i < N_NODES) g_scan_tmp[i] = s[tid] - v;
    if (tid == SCAN_B - 1) g_bsum[blockIdx.x] = s[tid];
}

// scan3: warp-parallel block-offset computation (no serial ptr-chase)
__global__ void scan3_kernel() {
    __shared__ int base;
    int tid = threadIdx.x;
    if (tid < 32) {
        int sum = 0;
        for (int b = tid; b < blockIdx.x; b += 32) sum += g_bsum[b];
        #pragma unroll
        for (int o = 16; o > 0; o >>= 1)
            sum += __shfl_down_sync(0xFFFFFFFFu, sum, o);
        if (tid == 0) {
            base = sum;
            if (blockIdx.x == 0) g_rowptr[N_NODES] = N_EDGES;
        }
    }
    __syncthreads();
    int i = blockIdx.x * SCAN_B + tid;
    if (i < N_NODES) {
        int v = g_scan_tmp[i] + base;
        g_rowptr[i] = v;
        g_cursor[i] = v;
    }
}

__global__ void fill_kernel(const int* __restrict__ ei) {
    int e = blockIdx.x * blockDim.x + threadIdx.x;
    if (e < N_EDGES) {
        int r = ei[e];
        int c = ei[e + N_EDGES];
        int pos = atomicAdd(&g_cursor[c], 1);
        float nr = g_dis[r] * g_dis[c];
        g_csr_pack[pos] = make_int2(r, __float_as_int(nr));
    }
}

// ---------------- SGEMM (scalar FFMA, double-buffered A tile) ------------
// C[M,64] = A[M,K] @ W[K,64], fp32 compute, output stored as fp16.
// A = x (sel==0) or g_tmpB (sel==1), both fp32.
// 128x64 block tile, 256 threads, microtile 8 rows x 4 cols, KC=16 2-stage.
template <int K>
__global__ __launch_bounds__(256, 3)
void gemm_kernel(const float* __restrict__ x, const float* __restrict__ W,
                 int sel, int M) {
    constexpr int KC = 16;
    constexpr int NCH = K / KC;
    constexpr int AST = 132;   // padded word stride per k-row (bank spread)
    __shared__ __align__(16) float Ws[K * 64];
    __shared__ __align__(16) float As[2][KC * AST];

    const float* __restrict__ A = (sel == 0) ? x : (const float*)g_tmpB;
    __half* __restrict__ C = g_tmpAh;

    const int tid = threadIdx.x;
    const int tx = tid & 15;    // cols tx*4 .. tx*4+3
    const int ty = tid >> 4;    // rows ty*8 .. ty*8+7
    const int row0 = blockIdx.x * 128;

    for (int i = tid; i < K * 16; i += 256)
        *(float4*)(Ws + i * 4) = *(const float4*)(W + i * 4);

    // prefetch lanes: 512 float4 slots per chunk (128 rows x 4 float4)
    const int lr0 = tid >> 2;            // rows 0..63
    const int lr1 = (tid + 256) >> 2;    // rows 64..127
    const int lq  = tid & 3;             // float4 index along KC

    float4 pre0 = make_float4(0.f, 0.f, 0.f, 0.f);
    float4 pre1 = make_float4(0.f, 0.f, 0.f, 0.f);
    if (row0 + lr0 < M)
        pre0 = *(const float4*)(A + (size_t)(row0 + lr0) * K + lq * 4);
    if (row0 + lr1 < M)
        pre1 = *(const float4*)(A + (size_t)(row0 + lr1) * K + lq * 4);
    {
        float* dst = &As[0][0];
        dst[(lq * 4 + 0) * AST + lr0] = pre0.x;
        dst[(lq * 4 + 1) * AST + lr0] = pre0.y;
        dst[(lq * 4 + 2) * AST + lr0] = pre0.z;
        dst[(lq * 4 + 3) * AST + lr0] = pre0.w;
        dst[(lq * 4 + 0) * AST + lr1] = pre1.x;
        dst[(lq * 4 + 1) * AST + lr1] = pre1.y;
        dst[(lq * 4 + 2) * AST + lr1] = pre1.z;
        dst[(lq * 4 + 3) * AST + lr1] = pre1.w;
    }
    __syncthreads();

    float acc[8][4];
    #pragma unroll
    for (int r = 0; r < 8; r++)
        #pragma unroll
        for (int c = 0; c < 4; c++) acc[r][c] = 0.f;

    #pragma unroll
    for (int c = 0; c < NCH; c++) {
        // issue next chunk's loads before computing current chunk
        if (c + 1 < NCH) {
            int kk = (c + 1) * KC;
            pre0 = make_float4(0.f, 0.f, 0.f, 0.f);
            pre1 = make_float4(0.f, 0.f, 0.f, 0.f);
            if (row0 + lr0 < M)
                pre0 = *(const float4*)(A + (size_t)(row0 + lr0) * K + kk + lq * 4);
            if (row0 + lr1 < M)
                pre1 = *(const float4*)(A + (size_t)(row0 + lr1) * K + kk + lq * 4);
        }

        const float* Ab = &As[c & 1][0];
        #pragma unroll
        for (int k = 0; k < KC; k++) {
            const float* ap = Ab + k * AST + ty * 8;
            float4 alo = *(const float4*)(ap);
            float4 ahi = *(const float4*)(ap + 4);
            float4 b   = *(const float4*)(Ws + (size_t)(c * KC + k) * 64 + tx * 4);
            float a[8] = {alo.x, alo.y, alo.z, alo.w, ahi.x, ahi.y, ahi.z, ahi.w};
            #pragma unroll
            for (int r = 0; r < 8; r++) {
                acc[r][0] += a[r] * b.x;
                acc[r][1] += a[r] * b.y;
                acc[r][2] += a[r] * b.z;
                acc[r][3] += a[r] * b.w;
            }
        }

        if (c + 1 < NCH) {
            float* dst = &As[(c + 1) & 1][0];
            dst[(lq * 4 + 0) * AST + lr0] = pre0.x;
            dst[(lq * 4 + 1) * AST + lr0] = pre0.y;
            dst[(lq * 4 + 2) * AST + lr0] = pre0.z;
            dst[(lq * 4 + 3) * AST + lr0] = pre0.w;
            dst[(lq * 4 + 0) * AST + lr1] = pre1.x;
            dst[(lq * 4 + 1) * AST + lr1] = pre1.y;
            dst[(lq * 4 + 2) * AST + lr1] = pre1.z;
            dst[(lq * 4 + 3) * AST + lr1] = pre1.w;
            __syncthreads();
        }
    }

    #pragma unroll
    for (int r = 0; r < 8; r++) {
        int grow = row0 + ty * 8 + r;
        if (grow < M) {
            __half2 h01 = __floats2half2_rn(acc[r][0], acc[r][1]);
            __half2 h23 = __floats2half2_rn(acc[r][2], acc[r][3]);
            uint2 pk;
            pk.x = *(uint32_t*)&h01;
            pk.y = *(uint32_t*)&h23;
            *(uint2*)(C + (size_t)grow * 64 + tx * 4) = pk;
        }
    }
}

// ---------------- aggregation: fp16 gather, fp32 accumulate --------------
// g_tmpB[i] = sum_in(tmpAh[src]*norm) + tmpAh[i]/deg + b, optional relu.
// one warp per node; lane owns 2 consecutive features (one half2)
__global__ void aggregate_kernel(const float* __restrict__ bias, int relu) {
    int warp = (blockIdx.x * blockDim.x + threadIdx.x) >> 5;
    if (warp >= N_NODES) return;
    int lane = threadIdx.x & 31;

    const __half* __restrict__ hW = g_tmpAh;
    float* __restrict__ out = g_tmpB;

    int start = g_rowptr[warp];
    int end   = g_rowptr[warp + 1];
    float d = g_dis[warp];
    float w = d * d;   // self loop weight = 1/deg

    float2 sf = __half22float2(*(const __half2*)(hW + (size_t)warp * 64 + lane * 2));
    float ax = sf.x * w, ay = sf.y * w;

    for (int k = start; k < end; k++) {
        int2 p = g_csr_pack[k];
        float nr = __int_as_float(p.y);
        float2 vf = __half22float2(*(const __half2*)(hW + (size_t)p.x * 64 + lane * 2));
        ax += vf.x * nr;
        ay += vf.y * nr;
    }

    ax += bias[lane * 2];
    ay += bias[lane * 2 + 1];
    if (relu) { ax = fmaxf(ax, 0.f); ay = fmaxf(ay, 0.f); }
    *(float2*)(out + (size_t)warp * 64 + lane * 2) = make_float2(ax, ay);
}

// ---------------- mean pool over sorted batch ----------------------------
__global__ void pool_kernel(const int* __restrict__ batch) {
    const float* __restrict__ h = g_tmpB;
    int col  = threadIdx.x & 63;
    int slot = threadIdx.x >> 6;
    int n0 = blockIdx.x * 512 + slot * 128;
    if (n0 >= N_NODES) return;
    int n1 = min(n0 + 128, N_NODES);

    float acc = 0.f, cnt = 0.f;
    int cur = batch[n0];
    for (int i = n0; i < n1; i++) {
        int g = batch[i];
        if (g != cur) {
            atomicAdd(&g_pool_sums[cur * 64 + col], acc);
            if (col == 0) atomicAdd(&g_pool_cnt[cur], cnt);
            cur = g; acc = 0.f; cnt = 0.f;
        }
        acc += h[(size_t)i * 64 + col];
        cnt += 1.f;
    }
    atomicAdd(&g_pool_sums[cur * 64 + col], acc);
    if (col == 0) atomicAdd(&g_pool_cnt[cur], cnt);
}

// ---------------- final linear -------------------------------------------
__global__ void final_kernel(const float* __restrict__ Wlin,
                             const float* __restrict__ blin,
                             float* __restrict__ out) {
    int tid = threadIdx.x;
    if (tid >= N_GRAPHS * N_OUT) return;
    int g = tid / N_OUT;
    int o = tid % N_OUT;
    float inv = 1.f / fmaxf(g_pool_cnt[g], 1.f);
    float acc = blin[o];
    #pragma unroll
    for (int c = 0; c < 64; c++)
        acc += g_pool_sums[g * 64 + c] * inv * Wlin[c * N_OUT + o];
    out[g * N_OUT + o] = acc;
}

// ---------------- launch --------------------------------------------------
extern "C" void kernel_launch(void* const* d_in, const int* in_sizes, int n_in,
                              void* d_out, int out_size) {
    const float* x    = (const float*)d_in[0];
    const int*   ei   = (const int*)d_in[1];
    const int*   batch= (const int*)d_in[2];
    const float* W1   = (const float*)d_in[3];
    const float* b1   = (const float*)d_in[4];
    const float* W2   = (const float*)d_in[5];
    const float* b2   = (const float*)d_in[6];
    const float* W3   = (const float*)d_in[7];
    const float* b3   = (const float*)d_in[8];
    const float* Wlin = (const float*)d_in[9];
    const float* blin = (const float*)d_in[10];
    float* out = (float*)d_out;

    const int EBLK = (N_EDGES + 255) / 256;
    const int NBLK = (N_NODES + 255) / 256;
    const int GEMM_BLK = (N_NODES + 127) / 128;
    const int AGG_BLK  = (N_NODES * 32 + 255) / 256;

    // launches 0..2: prep gemm1 doesn't depend on
    init_kernel<<<NBLK, 256>>>();                    // 0
    count_kernel<<<EBLK, 256>>>(ei);                 // 1
    scan1_kernel<<<N_SCAN_BLOCKS, SCAN_B>>>();       // 2

    // launch 3: big GEMM (x @ W1) — ncu capture slot (control)
    gemm_kernel<128><<<GEMM_BLK, 256>>>(x, W1, 0, N_NODES);   // 3

    // finish CSR build
    scan3_kernel<<<N_SCAN_BLOCKS, SCAN_B>>>();       // 4
    fill_kernel<<<EBLK, 256>>>(ei);                  // 5

    // layer 1 aggregation
    aggregate_kernel<<<AGG_BLK, 256>>>(b1, 1);
    // layer 2
    gemm_kernel<64><<<GEMM_BLK, 256>>>(x, W2, 1, N_NODES);
    aggregate_kernel<<<AGG_BLK, 256>>>(b2, 1);
    // layer 3
    gemm_kernel<64><<<GEMM_BLK, 256>>>(x, W3, 1, N_NODES);
    aggregate_kernel<<<AGG_BLK, 256>>>(b3, 0);

    // pool + head
    pool_kernel<<<(N_NODES + 511) / 512, 256>>>(batch);
    final_kernel<<<1, N_GRAPHS * N_OUT>>>(Wlin, blin, out);
}

// round 17
// speedup vs baseline: 1.0455x; 1.0285x over previous
#include <cuda_runtime.h>
#include <cuda_bf16.h>
#include <cuda_fp16.h>
#include <cstdint>

// Problem constants (fixed by the dataset)
#define N_NODES 100000
#define N_EDGES 1600000
#define N_FEAT  128
#define HIDDEN  64
#define N_OUT   10
#define N_GRAPHS 64

#define SCAN_B 1024
#define N_SCAN_BLOCKS ((N_NODES + SCAN_B - 1) / SCAN_B)   // 98

// ---------------- device scratch (static, no allocation) ----------------
__device__ int    g_deg[N_NODES];
__device__ float  g_dis[N_NODES];
__device__ int    g_rowptr[N_NODES + 1];
__device__ int    g_cursor[N_NODES];
__device__ int    g_scan_tmp[N_NODES];
__device__ int    g_bsum[N_SCAN_BLOCKS];
__device__ __align__(16) int2   g_csr_pack[N_EDGES];
__device__ __align__(16) __half g_tmpAh[(size_t)N_NODES * HIDDEN]; // h@W (fp16)
__device__ __align__(16) float  g_tmpB[(size_t)N_NODES * HIDDEN];  // aggregated h
__device__ float  g_pool_sums[N_GRAPHS * HIDDEN];
__device__ float  g_pool_cnt[N_GRAPHS];

// ---------------- init / CSR build --------------------------------------
__global__ void init_kernel() {
    int i = blockIdx.x * blockDim.x + threadIdx.x;
    if (i < N_NODES) g_deg[i] = 1;
    if (i < N_GRAPHS * HIDDEN) g_pool_sums[i] = 0.f;
    if (i < N_GRAPHS) g_pool_cnt[i] = 0.f;
}

__global__ void count_kernel(const int* __restrict__ ei) {
    int e = blockIdx.x * blockDim.x + threadIdx.x;
    if (e < N_EDGES) atomicAdd(&g_deg[ei[e + N_EDGES]], 1);
}

__global__ void scan1_kernel() {
    __shared__ int s[SCAN_B];
    int tid = threadIdx.x;
    int i = blockIdx.x * SCAN_B + tid;
    int deg = (i < N_NODES) ? g_deg[i] : 1;
    if (i < N_NODES) g_dis[i] = rsqrtf((float)deg);
    int v = deg - 1;
    s[tid] = v;
    __syncthreads();
    #pragma unroll
    for (int off = 1; off < SCAN_B; off <<= 1) {
        int t = (tid >= off) ? s[tid - off] : 0;
        __syncthreads();
        s[tid] += t;
        __syncthreads();
    }
    if (i < N_NODES) g_scan_tmp[i] = s[tid] - v;
    if (tid == SCAN_B - 1) g_bsum[blockIdx.x] = s[tid];
}

// scan3: warp-parallel block-offset computation
__global__ void scan3_kernel() {
    __shared__ int base;
    int tid = threadIdx.x;
    if (tid < 32) {
        int sum = 0;
        for (int b = tid; b < blockIdx.x; b += 32) sum += g_bsum[b];
        #pragma unroll
        for (int o = 16; o > 0; o >>= 1)
            sum += __shfl_down_sync(0xFFFFFFFFu, sum, o);
        if (tid == 0) {
            base = sum;
            if (blockIdx.x == 0) g_rowptr[N_NODES] = N_EDGES;
        }
    }
    __syncthreads();
    int i = blockIdx.x * SCAN_B + tid;
    if (i < N_NODES) {
        int v = g_scan_tmp[i] + base;
        g_rowptr[i] = v;
        g_cursor[i] = v;
    }
}

__global__ void fill_kernel(const int* __restrict__ ei) {
    int e = blockIdx.x * blockDim.x + threadIdx.x;
    if (e < N_EDGES) {
        int r = ei[e];
        int c = ei[e + N_EDGES];
        int pos = atomicAdd(&g_cursor[c], 1);
        float nr = g_dis[r] * g_dis[c];
        g_csr_pack[pos] = make_int2(r, __float_as_int(nr));
    }
}

// ---------------- SGEMM (scalar FFMA, double-buffered A tile) ------------
// C[M,64] = A[M,K] @ W[K,64], fp32 compute, output stored as fp16.
template <int K>
__global__ __launch_bounds__(256, 3)
void gemm_kernel(const float* __restrict__ x, const float* __restrict__ W,
                 int sel, int M) {
    constexpr int KC = 16;
    constexpr int NCH = K / KC;
    constexpr int AST = 132;
    __shared__ __align__(16) float Ws[K * 64];
    __shared__ __align__(16) float As[2][KC * AST];

    const float* __restrict__ A = (sel == 0) ? x : (const float*)g_tmpB;
    __half* __restrict__ C = g_tmpAh;

    const int tid = threadIdx.x;
    const int tx = tid & 15;
    const int ty = tid >> 4;
    const int row0 = blockIdx.x * 128;

    for (int i = tid; i < K * 16; i += 256)
        *(float4*)(Ws + i * 4) = *(const float4*)(W + i * 4);

    const int lr0 = tid >> 2;
    const int lr1 = (tid + 256) >> 2;
    const int lq  = tid & 3;

    float4 pre0 = make_float4(0.f, 0.f, 0.f, 0.f);
    float4 pre1 = make_float4(0.f, 0.f, 0.f, 0.f);
    if (row0 + lr0 < M)
        pre0 = *(const float4*)(A + (size_t)(row0 + lr0) * K + lq * 4);
    if (row0 + lr1 < M)
        pre1 = *(const float4*)(A + (size_t)(row0 + lr1) * K + lq * 4);
    {
        float* dst = &As[0][0];
        dst[(lq * 4 + 0) * AST + lr0] = pre0.x;
        dst[(lq * 4 + 1) * AST + lr0] = pre0.y;
        dst[(lq * 4 + 2) * AST + lr0] = pre0.z;
        dst[(lq * 4 + 3) * AST + lr0] = pre0.w;
        dst[(lq * 4 + 0) * AST + lr1] = pre1.x;
        dst[(lq * 4 + 1) * AST + lr1] = pre1.y;
        dst[(lq * 4 + 2) * AST + lr1] = pre1.z;
        dst[(lq * 4 + 3) * AST + lr1] = pre1.w;
    }
    __syncthreads();

    float acc[8][4];
    #pragma unroll
    for (int r = 0; r < 8; r++)
        #pragma unroll
        for (int c = 0; c < 4; c++) acc[r][c] = 0.f;

    #pragma unroll
    for (int c = 0; c < NCH; c++) {
        if (c + 1 < NCH) {
            int kk = (c + 1) * KC;
            pre0 = make_float4(0.f, 0.f, 0.f, 0.f);
            pre1 = make_float4(0.f, 0.f, 0.f, 0.f);
            if (row0 + lr0 < M)
                pre0 = *(const float4*)(A + (size_t)(row0 + lr0) * K + kk + lq * 4);
            if (row0 + lr1 < M)
                pre1 = *(const float4*)(A + (size_t)(row0 + lr1) * K + kk + lq * 4);
        }

        const float* Ab = &As[c & 1][0];
        #pragma unroll
        for (int k = 0; k < KC; k++) {
            const float* ap = Ab + k * AST + ty * 8;
            float4 alo = *(const float4*)(ap);
            float4 ahi = *(const float4*)(ap + 4);
            float4 b   = *(const float4*)(Ws + (size_t)(c * KC + k) * 64 + tx * 4);
            float a[8] = {alo.x, alo.y, alo.z, alo.w, ahi.x, ahi.y, ahi.z, ahi.w};
            #pragma unroll
            for (int r = 0; r < 8; r++) {
                acc[r][0] += a[r] * b.x;
                acc[r][1] += a[r] * b.y;
                acc[r][2] += a[r] * b.z;
                acc[r][3] += a[r] * b.w;
            }
        }

        if (c + 1 < NCH) {
            float* dst = &As[(c + 1) & 1][0];
            dst[(lq * 4 + 0) * AST + lr0] = pre0.x;
            dst[(lq * 4 + 1) * AST + lr0] = pre0.y;
            dst[(lq * 4 + 2) * AST + lr0] = pre0.z;
            dst[(lq * 4 + 3) * AST + lr0] = pre0.w;
            dst[(lq * 4 + 0) * AST + lr1] = pre1.x;
            dst[(lq * 4 + 1) * AST + lr1] = pre1.y;
            dst[(lq * 4 + 2) * AST + lr1] = pre1.z;
            dst[(lq * 4 + 3) * AST + lr1] = pre1.w;
            __syncthreads();
        }
    }

    #pragma unroll
    for (int r = 0; r < 8; r++) {
        int grow = row0 + ty * 8 + r;
        if (grow < M) {
            __half2 h01 = __floats2half2_rn(acc[r][0], acc[r][1]);
            __half2 h23 = __floats2half2_rn(acc[r][2], acc[r][3]);
            uint2 pk;
            pk.x = *(uint32_t*)&h01;
            pk.y = *(uint32_t*)&h23;
            *(uint2*)(C + (size_t)grow * 64 + tx * 4) = pk;
        }
    }
}

// ---------------- aggregation: fp16 gather, fp32 accumulate --------------
__global__ void aggregate_kernel(const float* __restrict__ bias, int relu) {
    int warp = (blockIdx.x * blockDim.x + threadIdx.x) >> 5;
    if (warp >= N_NODES) return;
    int lane = threadIdx.x & 31;

    const __half* __restrict__ hW = g_tmpAh;
    float* __restrict__ out = g_tmpB;

    int start = g_rowptr[warp];
    int end   = g_rowptr[warp + 1];
    float d = g_dis[warp];
    float w = d * d;

    float2 sf = __half22float2(*(const __half2*)(hW + (size_t)warp * 64 + lane * 2));
    float ax = sf.x * w, ay = sf.y * w;

    for (int k = start; k < end; k++) {
        int2 p = g_csr_pack[k];
        float nr = __int_as_float(p.y);
        float2 vf = __half22float2(*(const __half2*)(hW + (size_t)p.x * 64 + lane * 2));
        ax += vf.x * nr;
        ay += vf.y * nr;
    }

    ax += bias[lane * 2];
    ay += bias[lane * 2 + 1];
    if (relu) { ax = fmaxf(ax, 0.f); ay = fmaxf(ay, 0.f); }
    *(float2*)(out + (size_t)warp * 64 + lane * 2) = make_float2(ax, ay);
}

// ---------------- mean pool over sorted batch ----------------------------
__global__ void pool_kernel(const int* __restrict__ batch) {
    const float* __restrict__ h = g_tmpB;
    int col  = threadIdx.x & 63;
    int slot = threadIdx.x >> 6;
    int n0 = blockIdx.x * 512 + slot * 128;
    if (n0 >= N_NODES) return;
    int n1 = min(n0 + 128, N_NODES);

    float acc = 0.f, cnt = 0.f;
    int cur = batch[n0];
    for (int i = n0; i < n1; i++) {
        int g = batch[i];
        if (g != cur) {
            atomicAdd(&g_pool_sums[cur * 64 + col], acc);
            if (col == 0) atomicAdd(&g_pool_cnt[cur], cnt);
            cur = g; acc = 0.f; cnt = 0.f;
        }
        acc += h[(size_t)i * 64 + col];
        cnt += 1.f;
    }
    atomicAdd(&g_pool_sums[cur * 64 + col], acc);
    if (col == 0) atomicAdd(&g_pool_cnt[cur], cnt);
}

// ---------------- final linear -------------------------------------------
__global__ void final_kernel(const float* __restrict__ Wlin,
                             const float* __restrict__ blin,
                             float* __restrict__ out) {
    int tid = threadIdx.x;
    if (tid >= N_GRAPHS * N_OUT) return;
    int g = tid / N_OUT;
    int o = tid % N_OUT;
    float inv = 1.f / fmaxf(g_pool_cnt[g], 1.f);
    float acc = blin[o];
    #pragma unroll
    for (int c = 0; c < 64; c++)
        acc += g_pool_sums[g * 64 + c] * inv * Wlin[c * N_OUT + o];
    out[g * N_OUT + o] = acc;
}

// ---------------- launch --------------------------------------------------
extern "C" void kernel_launch(void* const* d_in, const int* in_sizes, int n_in,
                              void* d_out, int out_size) {
    const float* x    = (const float*)d_in[0];
    const int*   ei   = (const int*)d_in[1];
    const int*   batch= (const int*)d_in[2];
    const float* W1   = (const float*)d_in[3];
    const float* b1   = (const float*)d_in[4];
    const float* W2   = (const float*)d_in[5];
    const float* b2   = (const float*)d_in[6];
    const float* W3   = (const float*)d_in[7];
    const float* b3   = (const float*)d_in[8];
    const float* Wlin = (const float*)d_in[9];
    const float* blin = (const float*)d_in[10];
    float* out = (float*)d_out;

    const int EBLK = (N_EDGES + 255) / 256;
    const int NBLK = (N_NODES + 255) / 256;
    const int GEMM_BLK = (N_NODES + 127) / 128;
    const int AGG_BLK  = (N_NODES * 32 + 255) / 256;

    // Fork a side stream so the CSR-build chain overlaps gemm1.
    // (host-side objects; created per call, intentionally not destroyed —
    //  destroying a stream/event participating in an active capture is UB)
    cudaStream_t s2;
    cudaStreamCreateWithFlags(&s2, cudaStreamNonBlocking);
    cudaEvent_t eFork, eJoin;
    cudaEventCreateWithFlags(&eFork, cudaEventDisableTiming);
    cudaEventCreateWithFlags(&eJoin, cudaEventDisableTiming);

    cudaEventRecord(eFork, 0);
    cudaStreamWaitEvent(s2, eFork, 0);

    // CSR-build chain on side stream (depends only on edge_index)
    init_kernel<<<NBLK, 256, 0, s2>>>();
    count_kernel<<<EBLK, 256, 0, s2>>>(ei);
    scan1_kernel<<<N_SCAN_BLOCKS, SCAN_B, 0, s2>>>();
    scan3_kernel<<<N_SCAN_BLOCKS, SCAN_B, 0, s2>>>();
    fill_kernel<<<EBLK, 256, 0, s2>>>(ei);
    cudaEventRecord(eJoin, s2);

    // Main chain: gemm1 (depends only on x, W1) runs concurrently
    gemm_kernel<128><<<GEMM_BLK, 256>>>(x, W1, 0, N_NODES);
    cudaStreamWaitEvent(0, eJoin, 0);   // join before aggregation

    // layer 1 aggregation
    aggregate_kernel<<<AGG_BLK, 256>>>(b1, 1);
    // layer 2
    gemm_kernel<64><<<GEMM_BLK, 256>>>(x, W2, 1, N_NODES);
    aggregate_kernel<<<AGG_BLK, 256>>>(b2, 1);
    // layer 3
    gemm_kernel<64><<<GEMM_BLK, 256>>>(x, W3, 1, N_NODES);
    aggregate_kernel<<<AGG_BLK, 256>>>(b3, 0);

    // pool + head
    pool_kernel<<<(N_NODES + 511) / 512, 256>>>(batch);
    final_kernel<<<1, N_GRAPHS * N_OUT>>>(Wlin, blin, out);
}